// round 10
// baseline (speedup 1.0000x reference)
#include <cuda_runtime.h>
#include <cuda_bf16.h>
#include <math.h>
#include <stdint.h>

// Problem constants (fixed by setup_inputs: b=4096, d=128, b_l=2048)
#define N_TOT 8192
#define D_DIM 128
#define BL    2048

#define NTILES 2080     // 64*65/2 upper-triangular 128x128 tiles
#define PERSIST 296     // 2 CTAs per SM on 148-SM B200

// Global row layout: l1=[0,2048) u1=[2048,4096) l2=[4096,6144) u2=[6144,8192)

// Scratch (__device__ globals; no allocation allowed)
__device__ __nv_bfloat16 d_Xbf[N_TOT * D_DIM];
__device__ float d_norm[N_TOT];
__device__ float d_rowsum[N_TOT];
__device__ float d_A[BL];
__device__ float d_B[BL];
__device__ float d_C[BL];
__device__ float d_p1acc;
__device__ int   d_cnt[BL];
__device__ unsigned int d_tilectr;
__device__ unsigned int d_finctr;

__device__ __forceinline__ uint32_t smem_u32(const void* p) {
    uint32_t a;
    asm("{ .reg .u64 t; cvta.to.shared.u64 t, %1; cvt.u32.u64 %0, t; }" : "=r"(a) : "l"(p));
    return a;
}
__device__ __forceinline__ void ldsm_x4(uint32_t* r, uint32_t addr) {
    asm volatile("ldmatrix.sync.aligned.m8n8.x4.shared.b16 {%0,%1,%2,%3}, [%4];"
                 : "=r"(r[0]), "=r"(r[1]), "=r"(r[2]), "=r"(r[3]) : "r"(addr));
}
__device__ __forceinline__ void mma16816(float* d, const uint32_t* a, const uint32_t* b) {
    asm volatile("mma.sync.aligned.m16n8k16.row.col.f32.bf16.bf16.f32 "
                 "{%0,%1,%2,%3}, {%4,%5,%6,%7}, {%8,%9}, {%0,%1,%2,%3};"
                 : "+f"(d[0]), "+f"(d[1]), "+f"(d[2]), "+f"(d[3])
                 : "r"(a[0]), "r"(a[1]), "r"(a[2]), "r"(a[3]), "r"(b[0]), "r"(b[1]));
}
__device__ __forceinline__ void cp_async16(uint32_t s, const void* g) {
    size_t ga = __cvta_generic_to_global(g);
    asm volatile("cp.async.cg.shared.global [%0], [%1], 16;" :: "r"(s), "l"(ga) : "memory");
}
#define CP_COMMIT() asm volatile("cp.async.commit_group;" ::: "memory")
#define CP_WAIT0()  asm volatile("cp.async.wait_group 0;" ::: "memory")

__device__ __forceinline__ float frcp(float x) {
    float r;
    asm("rcp.approx.f32 %0, %1;" : "=f"(r) : "f"(x));
    return r;
}

// Decode linear tile id -> (ti, tj), tj >= ti, row ti has 64-ti tiles.
__device__ __forceinline__ void tile_decode(int t, int& ti, int& tj) {
    int r = (int)((129.0f - sqrtf(16641.0f - 8.0f * (float)t)) * 0.5f);
    if (r < 0) r = 0;
    while (64 * r - (r * (r - 1)) / 2 > t) r--;
    while (64 * (r + 1) - ((r + 1) * r) / 2 <= t) r++;
    ti = r;
    tj = r + (t - (64 * r - (r * (r - 1)) / 2));
}

// ---------------------------------------------------------------------------
// Prep: blocks 0..1023 do norms + bf16 convert (warp per row, zero rowsum);
// block 1024 does label histogram cnt + zeros accumulators/counters.
// ---------------------------------------------------------------------------
__global__ void prep_kernel(const float* __restrict__ X, const int* __restrict__ labels) {
    if (blockIdx.x == 1024) {
        __shared__ int hist[128];
        const int tid = threadIdx.x;
        if (tid < 128) hist[tid] = 0;
        __syncthreads();
        for (int j = tid; j < BL; j += blockDim.x) {
            int l = labels[j];
            if (l >= 0 && l < 128) atomicAdd(&hist[l], 1);
        }
        __syncthreads();
        for (int i = tid; i < BL; i += blockDim.x) {
            int l = labels[i];
            d_cnt[i] = (l >= 0 && l < 128) ? hist[l] : 1;
            d_A[i] = 0.f; d_B[i] = 0.f; d_C[i] = 0.f;
        }
        if (tid == 0) {
            d_p1acc = 0.f;
            d_tilectr = PERSIST;
            d_finctr = 0;
        }
        return;
    }
    int warp = (blockIdx.x * blockDim.x + threadIdx.x) >> 5;
    int lane = threadIdx.x & 31;
    float4 v = ((const float4*)(X + (size_t)warp * D_DIM))[lane];
    float s = v.x * v.x + v.y * v.y + v.z * v.z + v.w * v.w;
    __nv_bfloat162 p0 = __nv_bfloat162(__float2bfloat16_rn(v.x), __float2bfloat16_rn(v.y));
    __nv_bfloat162 p1 = __nv_bfloat162(__float2bfloat16_rn(v.z), __float2bfloat16_rn(v.w));
    uint2 pk;
    pk.x = *(uint32_t*)&p0;
    pk.y = *(uint32_t*)&p1;
    *(uint2*)(d_Xbf + (size_t)warp * D_DIM + lane * 4) = pk;
    #pragma unroll
    for (int o = 16; o > 0; o >>= 1) s += __shfl_xor_sync(0xffffffffu, s, o);
    if (lane == 0) { d_norm[warp] = s; d_rowsum[warp] = 0.f; }
}

// ---------------------------------------------------------------------------
// Persistent triangular GEMM + epilogue (R7 geometry: 256 thr, 2 CTA/SM,
// warp tile 32x64, single 64KB buffer, 2 barriers/tile) + fused finalize.
// ---------------------------------------------------------------------------
__global__ __launch_bounds__(256, 2) void gemm_kernel(const int* __restrict__ labels,
                                                      float* __restrict__ out) {
    extern __shared__ char smem[];
    __shared__ float nrow[2][128], ncol[2][128];
    __shared__ int lrow[2][128], lcol[2][128];
    __shared__ int s_nt, s_ti2, s_tj2;
    __shared__ float sred[2][8];
    __shared__ unsigned int s_rank;

    const uint32_t As = smem_u32(smem);
    const uint32_t Bs = As + 32768;
    const int tid = threadIdx.x;
    const int wid = tid >> 5;
    const int lane = tid & 31;

    // Warp layout: 4 (M) x 2 (N). Warp tile 32x64.
    const int mbase = (wid & 3) * 32;
    const int nbase = (wid >> 2) * 64;
    const int arow = mbase + (lane & 15);
    const int achunkbit = lane >> 4;
    const int sA = arow & 7;
    const uint32_t aBase0 = As + (uint32_t)arow * 256u;
    const uint32_t aBase1 = As + (uint32_t)(arow + 16) * 256u;
    const int brow_off = (lane & 7) + ((lane >> 4) << 3);
    const int bchunkbit = (lane >> 3) & 1;
    const int sB = brow_off & 7;
    const int g = lane >> 2, q = lane & 3;

    int ti, tj;
    tile_decode((int)blockIdx.x, ti, tj);
    int bi = 0;

    // ---- prologue: stage small arrays (buf 0) + load first tile ----
    {
        const int ib = ti * 128, jb = tj * 128;
        const bool nA = (tj < 16);
        const bool nB = (ti < 16) && (tj >= 32) && (tj < 48);
        const bool nC = (ti >= 32) && (ti < 48) && (tj < 48);
        if (tid < 128) {
            nrow[0][tid] = d_norm[ib + tid];
            if (nA || nB || nC) lrow[0][tid] = labels[(nC ? (ib - 4096) : ib) + tid];
        } else {
            const int t2 = tid - 128;
            ncol[0][t2] = d_norm[jb + t2];
            if (nA || nB || nC) lcol[0][t2] = labels[((nB || nC) ? (jb - 4096) : jb) + t2];
        }
        #pragma unroll
        for (int it = 0; it < 8; it++) {
            int idx = tid + it * 256;
            int r = idx >> 4, c = idx & 15;
            uint32_t dst = (uint32_t)r * 256u + (uint32_t)((c ^ (r & 7)) << 4);
            cp_async16(As + dst, d_Xbf + (size_t)(ib + r) * D_DIM + c * 8);
            cp_async16(Bs + dst, d_Xbf + (size_t)(jb + r) * D_DIM + c * 8);
        }
        CP_COMMIT();
        CP_WAIT0();
        __syncthreads();
    }

    while (true) {
        const int ibase = ti * 128, jbase = tj * 128;
        const bool diagTile = (ti == tj);
        const bool isA  = (tj < 16);
        const bool isB  = (ti < 16) && (tj >= 32) && (tj < 48);
        const bool isC  = (ti >= 32) && (ti < 48) && (tj < 48);
        const bool isP1 = (ti >= 16) && (ti < 32) && (tj == ti + 32);
        const bool needLab = isA || isB || isC;

        // Fetch next tile id (published at the post-mainloop barrier)
        if (tid == 0) {
            int n = (int)atomicAdd(&d_tilectr, 1u);
            s_nt = n;
            if (n < NTILES) {
                int a, b;
                tile_decode(n, a, b);
                s_ti2 = a; s_tj2 = b;
            }
        }

        // ---- mainloop ----
        float acc[2][8][4];
        #pragma unroll
        for (int m = 0; m < 2; m++)
            #pragma unroll
            for (int n = 0; n < 8; n++)
                #pragma unroll
                for (int r = 0; r < 4; r++) acc[m][n][r] = 0.f;

        #pragma unroll
        for (int kk = 0; kk < 8; kk++) {
            uint32_t a0[4], a1[4], bb[4];
            const uint32_t ac = (uint32_t)(((kk * 2 + achunkbit) ^ sA) << 4);
            ldsm_x4(a0, aBase0 + ac);
            ldsm_x4(a1, aBase1 + ac);
            const uint32_t bc = (uint32_t)(((kk * 2 + bchunkbit) ^ sB) << 4);
            #pragma unroll
            for (int nt4 = 0; nt4 < 4; nt4++) {
                ldsm_x4(bb, Bs + (uint32_t)(nbase + nt4 * 16 + brow_off) * 256u + bc);
                mma16816(acc[0][2 * nt4],     a0, bb);
                mma16816(acc[0][2 * nt4 + 1], a0, bb + 2);
                mma16816(acc[1][2 * nt4],     a1, bb);
                mma16816(acc[1][2 * nt4 + 1], a1, bb + 2);
            }
        }
        __syncthreads();   // As/Bs free; s_nt/s_ti2/s_tj2 visible

        const int tn = s_nt;
        const bool more = (tn < NTILES);
        const int ti2 = more ? s_ti2 : 0, tj2 = more ? s_tj2 : 0;
        if (more) {
            const int ib2 = ti2 * 128, jb2 = tj2 * 128;
            #pragma unroll
            for (int it = 0; it < 8; it++) {
                int idx = tid + it * 256;
                int r = idx >> 4, c = idx & 15;
                uint32_t dst = (uint32_t)r * 256u + (uint32_t)((c ^ (r & 7)) << 4);
                cp_async16(As + dst, d_Xbf + (size_t)(ib2 + r) * D_DIM + c * 8);
                cp_async16(Bs + dst, d_Xbf + (size_t)(jb2 + r) * D_DIM + c * 8);
            }
            CP_COMMIT();
            // stage next small arrays into the other buffer (no barrier needed)
            const bool nA2 = (tj2 < 16);
            const bool nB2 = (ti2 < 16) && (tj2 >= 32) && (tj2 < 48);
            const bool nC2 = (ti2 >= 32) && (ti2 < 48) && (tj2 < 48);
            const int bo = bi ^ 1;
            if (tid < 128) {
                nrow[bo][tid] = d_norm[ib2 + tid];
                if (nA2 || nB2 || nC2) lrow[bo][tid] = labels[(nC2 ? (ib2 - 4096) : ib2) + tid];
            } else {
                const int t2 = tid - 128;
                ncol[bo][t2] = d_norm[jb2 + t2];
                if (nA2 || nB2 || nC2) lcol[bo][t2] = labels[((nB2 || nC2) ? (jb2 - 4096) : jb2) + t2];
            }
        }

        // ---- epilogue (reads small buf bi; direct global REDG accumulation) --
        int   rloc[4];
        float nr1[4], rsum[4];
        #pragma unroll
        for (int m4 = 0; m4 < 4; m4++) {
            rloc[m4] = mbase + (m4 >> 1) * 16 + g + (m4 & 1) * 8;
            nr1[m4] = nrow[bi][rloc[m4]] + 1.0f;
            rsum[m4] = 0.f;
        }

        if (!needLab && !isP1) {
            // ---- lean path ----
            #pragma unroll
            for (int nt = 0; nt < 8; nt++) {
                #pragma unroll
                for (int e = 0; e < 2; e++) {
                    const int jl = nbase + nt * 8 + q * 2 + e;
                    const float nc = ncol[bi][jl];
                    float cs_local = 0.f;
                    #pragma unroll
                    for (int m4 = 0; m4 < 4; m4++) {
                        const float dot = acc[m4 >> 1][nt][2 * (m4 & 1) + e];
                        const float w = fmaxf(fmaf(-2.f, dot, nr1[m4] + nc), 1.f);
                        const float cv = frcp(w);
                        if (!(diagTile && (rloc[m4] == jl))) {
                            rsum[m4] += cv;
                            cs_local += cv;
                        }
                    }
                    if (!diagTile) {
                        cs_local += __shfl_xor_sync(0xffffffffu, cs_local, 4);
                        cs_local += __shfl_xor_sync(0xffffffffu, cs_local, 8);
                        cs_local += __shfl_xor_sync(0xffffffffu, cs_local, 16);
                        if (g == 0) atomicAdd(&d_rowsum[jbase + jl], cs_local);
                    }
                }
            }
        } else {
            // ---- generic path (label masks and/or p1 diagonal) ----
            int lr[4];
            #pragma unroll
            for (int m4 = 0; m4 < 4; m4++) lr[m4] = needLab ? lrow[bi][rloc[m4]] : 0;
            #pragma unroll
            for (int nt = 0; nt < 8; nt++) {
                #pragma unroll
                for (int e = 0; e < 2; e++) {
                    const int jl = nbase + nt * 8 + q * 2 + e;
                    const float nc = ncol[bi][jl];
                    const int lc = needLab ? lcol[bi][jl] : -12345;
                    float cs_local = 0.f;
                    #pragma unroll
                    for (int m4 = 0; m4 < 4; m4++) {
                        const float dot = acc[m4 >> 1][nt][2 * (m4 & 1) + e];
                        const float w = fmaxf(fmaf(-2.f, dot, nr1[m4] + nc), 1.f);
                        const float cv = frcp(w);
                        const bool self = diagTile && (rloc[m4] == jl);
                        if (!self) {
                            rsum[m4] += cv;
                            if (!diagTile) cs_local += cv;
                        }
                        if (needLab && lr[m4] == lc) {
                            if (isB) {
                                atomicAdd(&d_B[ibase + rloc[m4]], -__logf(w));
                            } else if (!self) {
                                const float lg = -__logf(w);
                                if (isA) {
                                    atomicAdd(&d_A[ibase + rloc[m4]], lg);
                                    if (!diagTile) atomicAdd(&d_A[jbase + jl], lg);
                                } else {
                                    atomicAdd(&d_C[ibase - 4096 + rloc[m4]], lg);
                                    if (!diagTile) atomicAdd(&d_C[jbase - 4096 + jl], lg);
                                }
                            }
                        }
                        if (isP1 && rloc[m4] == jl) atomicAdd(&d_p1acc, -__logf(w));
                    }
                    if (!diagTile) {
                        cs_local += __shfl_xor_sync(0xffffffffu, cs_local, 4);
                        cs_local += __shfl_xor_sync(0xffffffffu, cs_local, 8);
                        cs_local += __shfl_xor_sync(0xffffffffu, cs_local, 16);
                        if (g == 0) atomicAdd(&d_rowsum[jbase + jl], cs_local);
                    }
                }
            }
        }

        // Row sums: reduce over quad, then direct global REDG
        #pragma unroll
        for (int m4 = 0; m4 < 4; m4++) {
            float s = rsum[m4];
            s += __shfl_xor_sync(0xffffffffu, s, 1);
            s += __shfl_xor_sync(0xffffffffu, s, 2);
            if (q == 0) atomicAdd(&d_rowsum[ibase + rloc[m4]], s);
        }

        if (!more) break;
        CP_WAIT0();
        __syncthreads();   // As/Bs ready; staged small arrays visible
        ti = ti2; tj = tj2; bi ^= 1;
    }

    // ---- fused finalize: last-arriving CTA (all 296 are co-resident) ----
    __syncthreads();
    if (tid == 0) {
        __threadfence();
        s_rank = atomicAdd(&d_finctr, 1u);
    }
    __syncthreads();
    if (s_rank == PERSIST - 1) {
        __threadfence();
        float negsum = 0.f, possum = 0.f;
        for (int i = tid; i < N_TOT; i += 256) negsum += __logf(d_rowsum[i]);
        for (int i = tid; i < BL; i += 256) {
            const float denom = 2.f * (float)d_cnt[i] - 1.f;
            possum += (d_A[i] + 2.f * d_B[i] + d_C[i]) / denom;
        }
        #pragma unroll
        for (int o = 16; o > 0; o >>= 1) {
            negsum += __shfl_xor_sync(0xffffffffu, negsum, o);
            possum += __shfl_xor_sync(0xffffffffu, possum, o);
        }
        if (lane == 0) { sred[0][wid] = negsum; sred[1][wid] = possum; }
        __syncthreads();
        if (tid < 32) {
            negsum = (tid < 8) ? sred[0][tid] : 0.f;
            possum = (tid < 8) ? sred[1][tid] : 0.f;
            #pragma unroll
            for (int o = 4; o > 0; o >>= 1) {
                negsum += __shfl_xor_sync(0xffffffffu, negsum, o);
                possum += __shfl_xor_sync(0xffffffffu, possum, o);
            }
            if (tid == 0) {
                const float pos = possum / (float)N_TOT + d_p1acc / (float)(N_TOT / 2);
                const float neg = negsum / (float)N_TOT;
                out[0] = -(pos - neg);
            }
        }
    }
}

extern "C" void kernel_launch(void* const* d_in, const int* in_sizes, int n_in,
                              void* d_out, int out_size) {
    const float* X      = (const float*)d_in[0];
    const int*   labels = (const int*)d_in[1];
    (void)in_sizes; (void)n_in; (void)out_size;

    prep_kernel<<<1025, 256>>>(X, labels);

    cudaFuncSetAttribute(gemm_kernel, cudaFuncAttributeMaxDynamicSharedMemorySize, 65536);
    gemm_kernel<<<PERSIST, 256, 65536>>>(labels, (float*)d_out);
}

// round 11
// speedup vs baseline: 1.0700x; 1.0700x over previous
#include <cuda_runtime.h>
#include <cuda_bf16.h>
#include <math.h>
#include <stdint.h>

// Problem constants (fixed by setup_inputs: b=4096, d=128, b_l=2048)
#define N_TOT 8192
#define D_DIM 128
#define BL    2048

#define NTILES 2080     // 64*65/2 upper-triangular 128x128 tiles
#define PERSIST 444     // 3 CTAs per SM on 148-SM B200

// Global row layout: l1=[0,2048) u1=[2048,4096) l2=[4096,6144) u2=[6144,8192)

// Scratch (__device__ globals; no allocation allowed)
__device__ __nv_bfloat16 d_Xbf[N_TOT * D_DIM];
__device__ float d_norm[N_TOT];
__device__ float d_rowsum[N_TOT];
__device__ float d_A[BL];
__device__ float d_B[BL];
__device__ float d_C[BL];
__device__ float d_p1acc;
__device__ int   d_cnt[BL];
__device__ unsigned int d_tilectr;
__device__ unsigned int d_finctr;

__device__ __forceinline__ uint32_t smem_u32(const void* p) {
    uint32_t a;
    asm("{ .reg .u64 t; cvta.to.shared.u64 t, %1; cvt.u32.u64 %0, t; }" : "=r"(a) : "l"(p));
    return a;
}
__device__ __forceinline__ void ldsm_x4(uint32_t* r, uint32_t addr) {
    asm volatile("ldmatrix.sync.aligned.m8n8.x4.shared.b16 {%0,%1,%2,%3}, [%4];"
                 : "=r"(r[0]), "=r"(r[1]), "=r"(r[2]), "=r"(r[3]) : "r"(addr));
}
__device__ __forceinline__ void mma16816(float* d, const uint32_t* a, const uint32_t* b) {
    asm volatile("mma.sync.aligned.m16n8k16.row.col.f32.bf16.bf16.f32 "
                 "{%0,%1,%2,%3}, {%4,%5,%6,%7}, {%8,%9}, {%0,%1,%2,%3};"
                 : "+f"(d[0]), "+f"(d[1]), "+f"(d[2]), "+f"(d[3])
                 : "r"(a[0]), "r"(a[1]), "r"(a[2]), "r"(a[3]), "r"(b[0]), "r"(b[1]));
}
__device__ __forceinline__ void cp_async16(uint32_t s, const void* g) {
    size_t ga = __cvta_generic_to_global(g);
    asm volatile("cp.async.cg.shared.global [%0], [%1], 16;" :: "r"(s), "l"(ga) : "memory");
}
#define CP_COMMIT() asm volatile("cp.async.commit_group;" ::: "memory")
#define CP_WAIT0()  asm volatile("cp.async.wait_group 0;" ::: "memory")

__device__ __forceinline__ float frcp(float x) {
    float r;
    asm("rcp.approx.f32 %0, %1;" : "=f"(r) : "f"(x));
    return r;
}

// Decode linear tile id -> (ti, tj), tj >= ti, row ti has 64-ti tiles.
__device__ __forceinline__ void tile_decode(int t, int& ti, int& tj) {
    int r = (int)((129.0f - sqrtf(16641.0f - 8.0f * (float)t)) * 0.5f);
    if (r < 0) r = 0;
    while (64 * r - (r * (r - 1)) / 2 > t) r--;
    while (64 * (r + 1) - ((r + 1) * r) / 2 <= t) r++;
    ti = r;
    tj = r + (t - (64 * r - (r * (r - 1)) / 2));
}

// ---------------------------------------------------------------------------
// Prep: blocks 0..1023 do norms + bf16 convert (warp per row, zero rowsum);
// block 1024 does label histogram cnt + zeros accumulators/counters.
// ---------------------------------------------------------------------------
__global__ void prep_kernel(const float* __restrict__ X, const int* __restrict__ labels) {
    if (blockIdx.x == 1024) {
        __shared__ int hist[128];
        const int tid = threadIdx.x;
        if (tid < 128) hist[tid] = 0;
        __syncthreads();
        for (int j = tid; j < BL; j += blockDim.x) {
            int l = labels[j];
            if (l >= 0 && l < 128) atomicAdd(&hist[l], 1);
        }
        __syncthreads();
        for (int i = tid; i < BL; i += blockDim.x) {
            int l = labels[i];
            d_cnt[i] = (l >= 0 && l < 128) ? hist[l] : 1;
            d_A[i] = 0.f; d_B[i] = 0.f; d_C[i] = 0.f;
        }
        if (tid == 0) {
            d_p1acc = 0.f;
            d_tilectr = PERSIST;
            d_finctr = 0;
        }
        return;
    }
    int warp = (blockIdx.x * blockDim.x + threadIdx.x) >> 5;
    int lane = threadIdx.x & 31;
    float4 v = ((const float4*)(X + (size_t)warp * D_DIM))[lane];
    float s = v.x * v.x + v.y * v.y + v.z * v.z + v.w * v.w;
    __nv_bfloat162 p0 = __nv_bfloat162(__float2bfloat16_rn(v.x), __float2bfloat16_rn(v.y));
    __nv_bfloat162 p1 = __nv_bfloat162(__float2bfloat16_rn(v.z), __float2bfloat16_rn(v.w));
    uint2 pk;
    pk.x = *(uint32_t*)&p0;
    pk.y = *(uint32_t*)&p1;
    *(uint2*)(d_Xbf + (size_t)warp * D_DIM + lane * 4) = pk;
    #pragma unroll
    for (int o = 16; o > 0; o >>= 1) s += __shfl_xor_sync(0xffffffffu, s, o);
    if (lane == 0) { d_norm[warp] = s; d_rowsum[warp] = 0.f; }
}

// ---------------------------------------------------------------------------
// Persistent triangular GEMM + epilogue + fused finalize.
// 256 threads, 3 CTAs/SM (85-reg cap), CTA tile 128x128 processed in two
// 128x64 N-halves with 32x32 warp tiles (acc registers reused per half).
// Single 64KB buffer, 2 barriers/tile, dynamic scheduler, REDG accumulation.
// ---------------------------------------------------------------------------
__global__ __launch_bounds__(256, 3) void gemm_kernel(const int* __restrict__ labels,
                                                      float* __restrict__ out) {
    extern __shared__ char smem[];
    __shared__ float nrow[2][128], ncol[2][128];
    __shared__ int lrow[2][128], lcol[2][128];
    __shared__ int s_nt, s_ti2, s_tj2;
    __shared__ float sred[2][8];
    __shared__ unsigned int s_rank;

    const uint32_t As = smem_u32(smem);
    const uint32_t Bs = As + 32768;
    const int tid = threadIdx.x;
    const int wid = tid >> 5;
    const int lane = tid & 31;

    // Warp layout per half: 4 (M) x 2 (N). Warp tile 32x32.
    const int mbase = (wid & 3) * 32;
    const int nwarp = wid >> 2;                 // 0 or 1 within a 64-col half
    const int arow = mbase + (lane & 15);
    const int achunkbit = lane >> 4;
    const int sA = arow & 7;
    const uint32_t aBase0 = As + (uint32_t)arow * 256u;
    const uint32_t aBase1 = As + (uint32_t)(arow + 16) * 256u;
    const int brow_off = (lane & 7) + ((lane >> 4) << 3);
    const int bchunkbit = (lane >> 3) & 1;
    const int sB = brow_off & 7;
    const int g = lane >> 2, q = lane & 3;

    int ti, tj;
    tile_decode((int)blockIdx.x, ti, tj);
    int bi = 0;

    // ---- prologue: stage small arrays (buf 0) + load first tile ----
    {
        const int ib = ti * 128, jb = tj * 128;
        const bool nA = (tj < 16);
        const bool nB = (ti < 16) && (tj >= 32) && (tj < 48);
        const bool nC = (ti >= 32) && (ti < 48) && (tj < 48);
        if (tid < 128) {
            nrow[0][tid] = d_norm[ib + tid];
            if (nA || nB || nC) lrow[0][tid] = labels[(nC ? (ib - 4096) : ib) + tid];
        } else {
            const int t2 = tid - 128;
            ncol[0][t2] = d_norm[jb + t2];
            if (nA || nB || nC) lcol[0][t2] = labels[((nB || nC) ? (jb - 4096) : jb) + t2];
        }
        #pragma unroll
        for (int it = 0; it < 8; it++) {
            int idx = tid + it * 256;
            int r = idx >> 4, c = idx & 15;
            uint32_t dst = (uint32_t)r * 256u + (uint32_t)((c ^ (r & 7)) << 4);
            cp_async16(As + dst, d_Xbf + (size_t)(ib + r) * D_DIM + c * 8);
            cp_async16(Bs + dst, d_Xbf + (size_t)(jb + r) * D_DIM + c * 8);
        }
        CP_COMMIT();
        CP_WAIT0();
        __syncthreads();
    }

    while (true) {
        const int ibase = ti * 128, jbase = tj * 128;
        const bool diagTile = (ti == tj);
        const bool isA  = (tj < 16);
        const bool isB  = (ti < 16) && (tj >= 32) && (tj < 48);
        const bool isC  = (ti >= 32) && (ti < 48) && (tj < 48);
        const bool isP1 = (ti >= 16) && (ti < 32) && (tj == ti + 32);
        const bool needLab = isA || isB || isC;

        // Fetch next tile id (published at the post-mainloop barrier)
        if (tid == 0) {
            int n = (int)atomicAdd(&d_tilectr, 1u);
            s_nt = n;
            if (n < NTILES) {
                int a, b;
                tile_decode(n, a, b);
                s_ti2 = a; s_tj2 = b;
            }
        }

        // Per-row state (persists across both halves)
        int   rloc[4];
        float nr1[4], rsum[4];
        int   lr[4];
        #pragma unroll
        for (int m4 = 0; m4 < 4; m4++) {
            rloc[m4] = mbase + (m4 >> 1) * 16 + g + (m4 & 1) * 8;
            nr1[m4] = nrow[bi][rloc[m4]] + 1.0f;
            rsum[m4] = 0.f;
            lr[m4] = needLab ? lrow[bi][rloc[m4]] : 0;
        }

        int tn = 0, ti2 = 0, tj2 = 0;
        bool more = false;

        #pragma unroll
        for (int h = 0; h < 2; h++) {
            const int hbase = h * 64 + nwarp * 32;

            // ---- mainloop (this half: warp tile 32x32) ----
            float acc[2][4][4];
            #pragma unroll
            for (int m = 0; m < 2; m++)
                #pragma unroll
                for (int n = 0; n < 4; n++)
                    #pragma unroll
                    for (int r = 0; r < 4; r++) acc[m][n][r] = 0.f;

            const uint32_t bRow0 = Bs + (uint32_t)(hbase + brow_off) * 256u;
            const uint32_t bRow1 = Bs + (uint32_t)(hbase + 16 + brow_off) * 256u;
            #pragma unroll
            for (int kk = 0; kk < 8; kk++) {
                uint32_t a0[4], a1[4], b0[4], b1[4];
                const uint32_t ac = (uint32_t)(((kk * 2 + achunkbit) ^ sA) << 4);
                ldsm_x4(a0, aBase0 + ac);
                ldsm_x4(a1, aBase1 + ac);
                const uint32_t bc = (uint32_t)(((kk * 2 + bchunkbit) ^ sB) << 4);
                ldsm_x4(b0, bRow0 + bc);
                ldsm_x4(b1, bRow1 + bc);
                mma16816(acc[0][0], a0, b0);
                mma16816(acc[0][1], a0, b0 + 2);
                mma16816(acc[0][2], a0, b1);
                mma16816(acc[0][3], a0, b1 + 2);
                mma16816(acc[1][0], a1, b0);
                mma16816(acc[1][1], a1, b0 + 2);
                mma16816(acc[1][2], a1, b1);
                mma16816(acc[1][3], a1, b1 + 2);
            }

            if (h == 1) {
                // As/Bs fully consumed; scheduler slot visible after barrier
                __syncthreads();
                tn = s_nt;
                more = (tn < NTILES);
                ti2 = more ? s_ti2 : 0;
                tj2 = more ? s_tj2 : 0;
                if (more) {
                    const int ib2 = ti2 * 128, jb2 = tj2 * 128;
                    #pragma unroll
                    for (int it = 0; it < 8; it++) {
                        int idx = tid + it * 256;
                        int r = idx >> 4, c = idx & 15;
                        uint32_t dst = (uint32_t)r * 256u + (uint32_t)((c ^ (r & 7)) << 4);
                        cp_async16(As + dst, d_Xbf + (size_t)(ib2 + r) * D_DIM + c * 8);
                        cp_async16(Bs + dst, d_Xbf + (size_t)(jb2 + r) * D_DIM + c * 8);
                    }
                    CP_COMMIT();
                    const bool nA2 = (tj2 < 16);
                    const bool nB2 = (ti2 < 16) && (tj2 >= 32) && (tj2 < 48);
                    const bool nC2 = (ti2 >= 32) && (ti2 < 48) && (tj2 < 48);
                    const int bo = bi ^ 1;
                    if (tid < 128) {
                        nrow[bo][tid] = d_norm[ti2 * 128 + tid];
                        if (nA2 || nB2 || nC2) lrow[bo][tid] = labels[(nC2 ? (ti2 * 128 - 4096) : ti2 * 128) + tid];
                    } else {
                        const int t2 = tid - 128;
                        ncol[bo][t2] = d_norm[tj2 * 128 + t2];
                        if (nA2 || nB2 || nC2) lcol[bo][t2] = labels[((nB2 || nC2) ? (tj2 * 128 - 4096) : tj2 * 128) + t2];
                    }
                }
            }

            // ---- epilogue for this half ----
            if (!needLab && !isP1) {
                // lean path
                #pragma unroll
                for (int n8 = 0; n8 < 4; n8++) {
                    #pragma unroll
                    for (int e = 0; e < 2; e++) {
                        const int jl = hbase + n8 * 8 + q * 2 + e;
                        const float nc = ncol[bi][jl];
                        float cs_local = 0.f;
                        #pragma unroll
                        for (int m4 = 0; m4 < 4; m4++) {
                            const float dot = acc[m4 >> 1][n8][2 * (m4 & 1) + e];
                            const float w = fmaxf(fmaf(-2.f, dot, nr1[m4] + nc), 1.f);
                            const float cv = frcp(w);
                            if (!(diagTile && (rloc[m4] == jl))) {
                                rsum[m4] += cv;
                                cs_local += cv;
                            }
                        }
                        if (!diagTile) {
                            cs_local += __shfl_xor_sync(0xffffffffu, cs_local, 4);
                            cs_local += __shfl_xor_sync(0xffffffffu, cs_local, 8);
                            cs_local += __shfl_xor_sync(0xffffffffu, cs_local, 16);
                            if (g == 0) atomicAdd(&d_rowsum[jbase + jl], cs_local);
                        }
                    }
                }
            } else {
                // generic path (label masks and/or p1 diagonal)
                #pragma unroll
                for (int n8 = 0; n8 < 4; n8++) {
                    #pragma unroll
                    for (int e = 0; e < 2; e++) {
                        const int jl = hbase + n8 * 8 + q * 2 + e;
                        const float nc = ncol[bi][jl];
                        const int lc = needLab ? lcol[bi][jl] : -12345;
                        float cs_local = 0.f;
                        #pragma unroll
                        for (int m4 = 0; m4 < 4; m4++) {
                            const float dot = acc[m4 >> 1][n8][2 * (m4 & 1) + e];
                            const float w = fmaxf(fmaf(-2.f, dot, nr1[m4] + nc), 1.f);
                            const float cv = frcp(w);
                            const bool self = diagTile && (rloc[m4] == jl);
                            if (!self) {
                                rsum[m4] += cv;
                                if (!diagTile) cs_local += cv;
                            }
                            if (needLab && lr[m4] == lc) {
                                if (isB) {
                                    atomicAdd(&d_B[ibase + rloc[m4]], -__logf(w));
                                } else if (!self) {
                                    const float lg = -__logf(w);
                                    if (isA) {
                                        atomicAdd(&d_A[ibase + rloc[m4]], lg);
                                        if (!diagTile) atomicAdd(&d_A[jbase + jl], lg);
                                    } else {
                                        atomicAdd(&d_C[ibase - 4096 + rloc[m4]], lg);
                                        if (!diagTile) atomicAdd(&d_C[jbase - 4096 + jl], lg);
                                    }
                                }
                            }
                            if (isP1 && rloc[m4] == jl) atomicAdd(&d_p1acc, -__logf(w));
                        }
                        if (!diagTile) {
                            cs_local += __shfl_xor_sync(0xffffffffu, cs_local, 4);
                            cs_local += __shfl_xor_sync(0xffffffffu, cs_local, 8);
                            cs_local += __shfl_xor_sync(0xffffffffu, cs_local, 16);
                            if (g == 0) atomicAdd(&d_rowsum[jbase + jl], cs_local);
                        }
                    }
                }
            }
        }

        // Row sums: reduce over quad, then direct global REDG
        #pragma unroll
        for (int m4 = 0; m4 < 4; m4++) {
            float s = rsum[m4];
            s += __shfl_xor_sync(0xffffffffu, s, 1);
            s += __shfl_xor_sync(0xffffffffu, s, 2);
            if (q == 0) atomicAdd(&d_rowsum[ibase + rloc[m4]], s);
        }

        if (!more) break;
        CP_WAIT0();
        __syncthreads();   // next tile's As/Bs ready; staged small arrays visible
        ti = ti2; tj = tj2; bi ^= 1;
    }

    // ---- fused finalize: last-arriving CTA (all 444 are co-resident) ----
    __syncthreads();
    if (tid == 0) {
        __threadfence();
        s_rank = atomicAdd(&d_finctr, 1u);
    }
    __syncthreads();
    if (s_rank == PERSIST - 1) {
        __threadfence();
        float negsum = 0.f, possum = 0.f;
        for (int i = tid; i < N_TOT; i += 256) negsum += __logf(d_rowsum[i]);
        for (int i = tid; i < BL; i += 256) {
            const float denom = 2.f * (float)d_cnt[i] - 1.f;
            possum += (d_A[i] + 2.f * d_B[i] + d_C[i]) / denom;
        }
        #pragma unroll
        for (int o = 16; o > 0; o >>= 1) {
            negsum += __shfl_xor_sync(0xffffffffu, negsum, o);
            possum += __shfl_xor_sync(0xffffffffu, possum, o);
        }
        if (lane == 0) { sred[0][wid] = negsum; sred[1][wid] = possum; }
        __syncthreads();
        if (tid < 32) {
            negsum = (tid < 8) ? sred[0][tid] : 0.f;
            possum = (tid < 8) ? sred[1][tid] : 0.f;
            #pragma unroll
            for (int o = 4; o > 0; o >>= 1) {
                negsum += __shfl_xor_sync(0xffffffffu, negsum, o);
                possum += __shfl_xor_sync(0xffffffffu, possum, o);
            }
            if (tid == 0) {
                const float pos = possum / (float)N_TOT + d_p1acc / (float)(N_TOT / 2);
                const float neg = negsum / (float)N_TOT;
                out[0] = -(pos - neg);
            }
        }
    }
}

extern "C" void kernel_launch(void* const* d_in, const int* in_sizes, int n_in,
                              void* d_out, int out_size) {
    const float* X      = (const float*)d_in[0];
    const int*   labels = (const int*)d_in[1];
    (void)in_sizes; (void)n_in; (void)out_size;

    prep_kernel<<<1025, 256>>>(X, labels);

    cudaFuncSetAttribute(gemm_kernel, cudaFuncAttributeMaxDynamicSharedMemorySize, 65536);
    gemm_kernel<<<PERSIST, 256, 65536>>>(labels, (float*)d_out);
}

// round 12
// speedup vs baseline: 1.1223x; 1.0488x over previous
#include <cuda_runtime.h>
#include <cuda_bf16.h>
#include <math.h>
#include <stdint.h>

// Problem constants (fixed by setup_inputs: b=4096, d=128, b_l=2048)
#define N_TOT 8192
#define D_DIM 128
#define BL    2048

#define NTILES 2080     // 64*65/2 upper-triangular 128x128 tiles
#define PERSIST 444     // 3 CTAs per SM on 148-SM B200

// Global row layout: l1=[0,2048) u1=[2048,4096) l2=[4096,6144) u2=[6144,8192)

// Scratch (__device__ globals; no allocation allowed)
// d_Xbf holds bf16 X with per-row 16B-chunk swizzle: chunk c stored at c^(row&7)
__device__ __nv_bfloat16 d_Xbf[N_TOT * D_DIM];
__device__ float d_norm[N_TOT];
__device__ float d_rowsum[N_TOT];
__device__ float d_A[BL];
__device__ float d_B[BL];
__device__ float d_C[BL];
__device__ float d_p1acc;
__device__ int   d_cnt[BL];
__device__ unsigned int d_tilectr;
__device__ unsigned int d_finctr;

__device__ __forceinline__ uint32_t smem_u32(const void* p) {
    uint32_t a;
    asm("{ .reg .u64 t; cvta.to.shared.u64 t, %1; cvt.u32.u64 %0, t; }" : "=r"(a) : "l"(p));
    return a;
}
__device__ __forceinline__ void ldsm_x4(uint32_t* r, uint32_t addr) {
    asm volatile("ldmatrix.sync.aligned.m8n8.x4.shared.b16 {%0,%1,%2,%3}, [%4];"
                 : "=r"(r[0]), "=r"(r[1]), "=r"(r[2]), "=r"(r[3]) : "r"(addr));
}
__device__ __forceinline__ void mma16816(float* d, const uint32_t* a, const uint32_t* b) {
    asm volatile("mma.sync.aligned.m16n8k16.row.col.f32.bf16.bf16.f32 "
                 "{%0,%1,%2,%3}, {%4,%5,%6,%7}, {%8,%9}, {%0,%1,%2,%3};"
                 : "+f"(d[0]), "+f"(d[1]), "+f"(d[2]), "+f"(d[3])
                 : "r"(a[0]), "r"(a[1]), "r"(a[2]), "r"(a[3]), "r"(b[0]), "r"(b[1]));
}

// Bulk async copy (sm_90+): one instruction per tile, completes on mbarrier.
__device__ __forceinline__ void bulk_cp(uint32_t dst_smem, const void* src_gmem,
                                        uint32_t bytes, uint32_t mbar) {
    asm volatile("cp.async.bulk.shared::cta.global.mbarrier::complete_tx::bytes "
                 "[%0], [%1], %2, [%3];"
                 :: "r"(dst_smem), "l"(src_gmem), "r"(bytes), "r"(mbar) : "memory");
}
#define MBAR_INIT(mb, c)  asm volatile("mbarrier.init.shared.b64 [%0], %1;" :: "r"(mb), "r"(c) : "memory")
#define MBAR_EXPECT_TX(mb, tx) \
    asm volatile("mbarrier.arrive.expect_tx.shared.b64 _, [%0], %1;" :: "r"(mb), "r"(tx) : "memory")
#define MBAR_WAIT(mb, ph) do {                                                  \
    uint32_t _m = (mb), _p = (ph), _done;                                       \
    asm volatile("{ .reg .pred p; mbarrier.try_wait.parity.acquire.cta.shared::cta.b64 p, [%1], %2; selp.b32 %0, 1, 0, p; }" \
        : "=r"(_done) : "r"(_m), "r"(_p) : "memory");                           \
    if (!_done) {                                                               \
        asm volatile("{ .reg .pred P1; WL_%=: mbarrier.try_wait.parity.acquire.cta.shared::cta.b64 P1, [%0], %1, 0x989680; @P1 bra.uni WD_%=; bra.uni WL_%=; WD_%=: }" \
            :: "r"(_m), "r"(_p) : "memory");                                    \
    }                                                                           \
} while (0)

__device__ __forceinline__ float frcp(float x) {
    float r;
    asm("rcp.approx.f32 %0, %1;" : "=f"(r) : "f"(x));
    return r;
}

// Decode linear tile id -> (ti, tj), tj >= ti, row ti has 64-ti tiles.
__device__ __forceinline__ void tile_decode(int t, int& ti, int& tj) {
    int r = (int)((129.0f - sqrtf(16641.0f - 8.0f * (float)t)) * 0.5f);
    if (r < 0) r = 0;
    while (64 * r - (r * (r - 1)) / 2 > t) r--;
    while (64 * (r + 1) - ((r + 1) * r) / 2 <= t) r++;
    ti = r;
    tj = r + (t - (64 * r - (r * (r - 1)) / 2));
}

// ---------------------------------------------------------------------------
// Prep: blocks 0..1023 do norms + bf16 convert into SWIZZLED layout;
// block 1024 does label histogram cnt + zeros accumulators/counters.
// ---------------------------------------------------------------------------
__global__ void prep_kernel(const float* __restrict__ X, const int* __restrict__ labels) {
    if (blockIdx.x == 1024) {
        __shared__ int hist[128];
        const int tid = threadIdx.x;
        if (tid < 128) hist[tid] = 0;
        __syncthreads();
        for (int j = tid; j < BL; j += blockDim.x) {
            int l = labels[j];
            if (l >= 0 && l < 128) atomicAdd(&hist[l], 1);
        }
        __syncthreads();
        for (int i = tid; i < BL; i += blockDim.x) {
            int l = labels[i];
            d_cnt[i] = (l >= 0 && l < 128) ? hist[l] : 1;
            d_A[i] = 0.f; d_B[i] = 0.f; d_C[i] = 0.f;
        }
        if (tid == 0) {
            d_p1acc = 0.f;
            d_tilectr = PERSIST;
            d_finctr = 0;
        }
        return;
    }
    int warp = (blockIdx.x * blockDim.x + threadIdx.x) >> 5;   // = global row
    int lane = threadIdx.x & 31;
    float4 v = ((const float4*)(X + (size_t)warp * D_DIM))[lane];
    float s = v.x * v.x + v.y * v.y + v.z * v.z + v.w * v.w;
    __nv_bfloat162 p0 = __nv_bfloat162(__float2bfloat16_rn(v.x), __float2bfloat16_rn(v.y));
    __nv_bfloat162 p1 = __nv_bfloat162(__float2bfloat16_rn(v.z), __float2bfloat16_rn(v.w));
    uint2 pk;
    pk.x = *(uint32_t*)&p0;
    pk.y = *(uint32_t*)&p1;
    // lane covers 8 bytes = half of 16B chunk (lane>>1); store chunk at c^(row&7)
    const int sc = (lane >> 1) ^ (warp & 7);
    *(uint2*)(d_Xbf + (size_t)warp * D_DIM + sc * 8 + (lane & 1) * 4) = pk;
    #pragma unroll
    for (int o = 16; o > 0; o >>= 1) s += __shfl_xor_sync(0xffffffffu, s, o);
    if (lane == 0) { d_norm[warp] = s; d_rowsum[warp] = 0.f; }
}

// ---------------------------------------------------------------------------
// Persistent triangular GEMM + epilogue + fused finalize.
// 256 threads, 3 CTAs/SM, CTA tile 128x128 in two 128x64 N-halves.
// Tile loads via cp.async.bulk (2 instructions/tile) + mbarrier.
// ---------------------------------------------------------------------------
__global__ __launch_bounds__(256, 3) void gemm_kernel(const int* __restrict__ labels,
                                                      float* __restrict__ out) {
    extern __shared__ char smem[];
    __shared__ float nrow[2][128], ncol[2][128];
    __shared__ int lrow[2][128], lcol[2][128];
    __shared__ int s_nt, s_ti2, s_tj2;
    __shared__ float sred[2][8];
    __shared__ unsigned int s_rank;
    __shared__ __align__(8) unsigned long long s_mbar;

    const uint32_t As = smem_u32(smem);
    const uint32_t Bs = As + 32768;
    const uint32_t mb = smem_u32(&s_mbar);
    const int tid = threadIdx.x;
    const int wid = tid >> 5;
    const int lane = tid & 31;

    // Warp layout per half: 4 (M) x 2 (N). Warp tile 32x32.
    const int mbase = (wid & 3) * 32;
    const int nwarp = wid >> 2;
    const int arow = mbase + (lane & 15);
    const int achunkbit = lane >> 4;
    const int sA = arow & 7;
    const uint32_t aBase0 = As + (uint32_t)arow * 256u;
    const uint32_t aBase1 = As + (uint32_t)(arow + 16) * 256u;
    const int brow_off = (lane & 7) + ((lane >> 4) << 3);
    const int bchunkbit = (lane >> 3) & 1;
    const int sB = brow_off & 7;
    const int g = lane >> 2, q = lane & 3;

    int ti, tj;
    tile_decode((int)blockIdx.x, ti, tj);
    int bi = 0;
    int ph = 0;

    // ---- prologue ----
    {
        if (tid == 0) MBAR_INIT(mb, 1);
        const int ib = ti * 128, jb = tj * 128;
        const bool nA = (tj < 16);
        const bool nB = (ti < 16) && (tj >= 32) && (tj < 48);
        const bool nC = (ti >= 32) && (ti < 48) && (tj < 48);
        if (tid < 128) {
            nrow[0][tid] = d_norm[ib + tid];
            if (nA || nB || nC) lrow[0][tid] = labels[(nC ? (ib - 4096) : ib) + tid];
        } else {
            const int t2 = tid - 128;
            ncol[0][t2] = d_norm[jb + t2];
            if (nA || nB || nC) lcol[0][t2] = labels[((nB || nC) ? (jb - 4096) : jb) + t2];
        }
        __syncthreads();   // mbar init + small arrays visible
        if (tid == 0) {
            MBAR_EXPECT_TX(mb, 65536u);
            bulk_cp(As, d_Xbf + (size_t)ib * D_DIM, 32768u, mb);
            bulk_cp(Bs, d_Xbf + (size_t)jb * D_DIM, 32768u, mb);
        }
        MBAR_WAIT(mb, 0);
        ph = 1;
    }

    while (true) {
        const int ibase = ti * 128, jbase = tj * 128;
        const bool diagTile = (ti == tj);
        const bool isA  = (tj < 16);
        const bool isB  = (ti < 16) && (tj >= 32) && (tj < 48);
        const bool isC  = (ti >= 32) && (ti < 48) && (tj < 48);
        const bool isP1 = (ti >= 16) && (ti < 32) && (tj == ti + 32);
        const bool needLab = isA || isB || isC;

        // Fetch next tile id (published at the post-mainloop barrier)
        if (tid == 0) {
            int n = (int)atomicAdd(&d_tilectr, 1u);
            s_nt = n;
            if (n < NTILES) {
                int a, b;
                tile_decode(n, a, b);
                s_ti2 = a; s_tj2 = b;
            }
        }

        // Per-row state (persists across both halves)
        int   rloc[4];
        float nr1[4], rsum[4];
        int   lr[4];
        #pragma unroll
        for (int m4 = 0; m4 < 4; m4++) {
            rloc[m4] = mbase + (m4 >> 1) * 16 + g + (m4 & 1) * 8;
            nr1[m4] = nrow[bi][rloc[m4]] + 1.0f;
            rsum[m4] = 0.f;
            lr[m4] = needLab ? lrow[bi][rloc[m4]] : 0;
        }

        int tn = 0, ti2 = 0, tj2 = 0;
        bool more = false;

        #pragma unroll
        for (int h = 0; h < 2; h++) {
            const int hbase = h * 64 + nwarp * 32;

            // ---- mainloop (this half: warp tile 32x32) ----
            float acc[2][4][4];
            #pragma unroll
            for (int m = 0; m < 2; m++)
                #pragma unroll
                for (int n = 0; n < 4; n++)
                    #pragma unroll
                    for (int r = 0; r < 4; r++) acc[m][n][r] = 0.f;

            const uint32_t bRow0 = Bs + (uint32_t)(hbase + brow_off) * 256u;
            const uint32_t bRow1 = Bs + (uint32_t)(hbase + 16 + brow_off) * 256u;
            #pragma unroll
            for (int kk = 0; kk < 8; kk++) {
                uint32_t a0[4], a1[4], b0[4], b1[4];
                const uint32_t ac = (uint32_t)(((kk * 2 + achunkbit) ^ sA) << 4);
                ldsm_x4(a0, aBase0 + ac);
                ldsm_x4(a1, aBase1 + ac);
                const uint32_t bc = (uint32_t)(((kk * 2 + bchunkbit) ^ sB) << 4);
                ldsm_x4(b0, bRow0 + bc);
                ldsm_x4(b1, bRow1 + bc);
                mma16816(acc[0][0], a0, b0);
                mma16816(acc[0][1], a0, b0 + 2);
                mma16816(acc[0][2], a0, b1);
                mma16816(acc[0][3], a0, b1 + 2);
                mma16816(acc[1][0], a1, b0);
                mma16816(acc[1][1], a1, b0 + 2);
                mma16816(acc[1][2], a1, b1);
                mma16816(acc[1][3], a1, b1 + 2);
            }

            if (h == 1) {
                // All warps done reading As/Bs; scheduler slot visible
                __syncthreads();
                tn = s_nt;
                more = (tn < NTILES);
                ti2 = more ? s_ti2 : 0;
                tj2 = more ? s_tj2 : 0;
                if (more) {
                    if (tid == 0) {
                        MBAR_EXPECT_TX(mb, 65536u);
                        bulk_cp(As, d_Xbf + (size_t)(ti2 * 128) * D_DIM, 32768u, mb);
                        bulk_cp(Bs, d_Xbf + (size_t)(tj2 * 128) * D_DIM, 32768u, mb);
                    }
                    const bool nA2 = (tj2 < 16);
                    const bool nB2 = (ti2 < 16) && (tj2 >= 32) && (tj2 < 48);
                    const bool nC2 = (ti2 >= 32) && (ti2 < 48) && (tj2 < 48);
                    const int bo = bi ^ 1;
                    if (tid < 128) {
                        nrow[bo][tid] = d_norm[ti2 * 128 + tid];
                        if (nA2 || nB2 || nC2) lrow[bo][tid] = labels[(nC2 ? (ti2 * 128 - 4096) : ti2 * 128) + tid];
                    } else {
                        const int t2 = tid - 128;
                        ncol[bo][t2] = d_norm[tj2 * 128 + t2];
                        if (nA2 || nB2 || nC2) lcol[bo][t2] = labels[((nB2 || nC2) ? (tj2 * 128 - 4096) : tj2 * 128) + t2];
                    }
                }
            }

            // ---- epilogue for this half ----
            if (!needLab && !isP1) {
                // lean path
                #pragma unroll
                for (int n8 = 0; n8 < 4; n8++) {
                    #pragma unroll
                    for (int e = 0; e < 2; e++) {
                        const int jl = hbase + n8 * 8 + q * 2 + e;
                        const float nc = ncol[bi][jl];
                        float cs_local = 0.f;
                        #pragma unroll
                        for (int m4 = 0; m4 < 4; m4++) {
                            const float dot = acc[m4 >> 1][n8][2 * (m4 & 1) + e];
                            const float w = fmaxf(fmaf(-2.f, dot, nr1[m4] + nc), 1.f);
                            const float cv = frcp(w);
                            if (!(diagTile && (rloc[m4] == jl))) {
                                rsum[m4] += cv;
                                cs_local += cv;
                            }
                        }
                        if (!diagTile) {
                            cs_local += __shfl_xor_sync(0xffffffffu, cs_local, 4);
                            cs_local += __shfl_xor_sync(0xffffffffu, cs_local, 8);
                            cs_local += __shfl_xor_sync(0xffffffffu, cs_local, 16);
                            if (g == 0) atomicAdd(&d_rowsum[jbase + jl], cs_local);
                        }
                    }
                }
            } else {
                // generic path (label masks and/or p1 diagonal)
                #pragma unroll
                for (int n8 = 0; n8 < 4; n8++) {
                    #pragma unroll
                    for (int e = 0; e < 2; e++) {
                        const int jl = hbase + n8 * 8 + q * 2 + e;
                        const float nc = ncol[bi][jl];
                        const int lc = needLab ? lcol[bi][jl] : -12345;
                        float cs_local = 0.f;
                        #pragma unroll
                        for (int m4 = 0; m4 < 4; m4++) {
                            const float dot = acc[m4 >> 1][n8][2 * (m4 & 1) + e];
                            const float w = fmaxf(fmaf(-2.f, dot, nr1[m4] + nc), 1.f);
                            const float cv = frcp(w);
                            const bool self = diagTile && (rloc[m4] == jl);
                            if (!self) {
                                rsum[m4] += cv;
                                if (!diagTile) cs_local += cv;
                            }
                            if (needLab && lr[m4] == lc) {
                                if (isB) {
                                    atomicAdd(&d_B[ibase + rloc[m4]], -__logf(w));
                                } else if (!self) {
                                    const float lg = -__logf(w);
                                    if (isA) {
                                        atomicAdd(&d_A[ibase + rloc[m4]], lg);
                                        if (!diagTile) atomicAdd(&d_A[jbase + jl], lg);
                                    } else {
                                        atomicAdd(&d_C[ibase - 4096 + rloc[m4]], lg);
                                        if (!diagTile) atomicAdd(&d_C[jbase - 4096 + jl], lg);
                                    }
                                }
                            }
                            if (isP1 && rloc[m4] == jl) atomicAdd(&d_p1acc, -__logf(w));
                        }
                        if (!diagTile) {
                            cs_local += __shfl_xor_sync(0xffffffffu, cs_local, 4);
                            cs_local += __shfl_xor_sync(0xffffffffu, cs_local, 8);
                            cs_local += __shfl_xor_sync(0xffffffffu, cs_local, 16);
                            if (g == 0) atomicAdd(&d_rowsum[jbase + jl], cs_local);
                        }
                    }
                }
            }
        }

        // Row sums: reduce over quad, then direct global REDG
        #pragma unroll
        for (int m4 = 0; m4 < 4; m4++) {
            float s = rsum[m4];
            s += __shfl_xor_sync(0xffffffffu, s, 1);
            s += __shfl_xor_sync(0xffffffffu, s, 2);
            if (q == 0) atomicAdd(&d_rowsum[ibase + rloc[m4]], s);
        }

        if (!more) break;
        MBAR_WAIT(mb, ph);
        ph ^= 1;
        __syncthreads();   // staged small arrays visible
        ti = ti2; tj = tj2; bi ^= 1;
    }

    // ---- fused finalize: last-arriving CTA (all 444 are co-resident) ----
    __syncthreads();
    if (tid == 0) {
        __threadfence();
        s_rank = atomicAdd(&d_finctr, 1u);
    }
    __syncthreads();
    if (s_rank == PERSIST - 1) {
        __threadfence();
        float negsum = 0.f, possum = 0.f;
        for (int i = tid; i < N_TOT; i += 256) negsum += __logf(d_rowsum[i]);
        for (int i = tid; i < BL; i += 256) {
            const float denom = 2.f * (float)d_cnt[i] - 1.f;
            possum += (d_A[i] + 2.f * d_B[i] + d_C[i]) / denom;
        }
        #pragma unroll
        for (int o = 16; o > 0; o >>= 1) {
            negsum += __shfl_xor_sync(0xffffffffu, negsum, o);
            possum += __shfl_xor_sync(0xffffffffu, possum, o);
        }
        if (lane == 0) { sred[0][wid] = negsum; sred[1][wid] = possum; }
        __syncthreads();
        if (tid < 32) {
            negsum = (tid < 8) ? sred[0][tid] : 0.f;
            possum = (tid < 8) ? sred[1][tid] : 0.f;
            #pragma unroll
            for (int o = 4; o > 0; o >>= 1) {
                negsum += __shfl_xor_sync(0xffffffffu, negsum, o);
                possum += __shfl_xor_sync(0xffffffffu, possum, o);
            }
            if (tid == 0) {
                const float pos = possum / (float)N_TOT + d_p1acc / (float)(N_TOT / 2);
                const float neg = negsum / (float)N_TOT;
                out[0] = -(pos - neg);
            }
        }
    }
}

extern "C" void kernel_launch(void* const* d_in, const int* in_sizes, int n_in,
                              void* d_out, int out_size) {
    const float* X      = (const float*)d_in[0];
    const int*   labels = (const int*)d_in[1];
    (void)in_sizes; (void)n_in; (void)out_size;

    prep_kernel<<<1025, 256>>>(X, labels);

    cudaFuncSetAttribute(gemm_kernel, cudaFuncAttributeMaxDynamicSharedMemorySize, 65536);
    gemm_kernel<<<PERSIST, 256, 65536>>>(labels, (float*)d_out);
}